// round 10
// baseline (speedup 1.0000x reference)
#include <cuda_runtime.h>

#define Bsz 64
#define Tsz 512
#define Dsz 1024
#define Usz 1024
#define NCTA 128

// Double-buffered transposed hidden state: hT[buf][k*64 + b]
__device__ __align__(16) float g_hT[2][Usz * Bsz];
__device__ volatile unsigned int g_flag[NCTA];

// ---------------------------------------------------------------------------
// Packed fp32x2 helpers (sm_100+). Numerics identical to scalar FFMA.
// ---------------------------------------------------------------------------
__device__ __forceinline__ unsigned long long pk2(float lo, float hi)
{
    unsigned long long d;
    asm("mov.b64 %0, {%1, %2};" : "=l"(d) : "f"(lo), "f"(hi));
    return d;
}
__device__ __forceinline__ unsigned long long ffma2(unsigned long long a,
                                                    unsigned long long b,
                                                    unsigned long long c)
{
    unsigned long long d;
    asm("fma.rn.f32x2 %0, %1, %2, %3;" : "=l"(d) : "l"(a), "l"(b), "l"(c));
    return d;
}
__device__ __forceinline__ unsigned long long fadd2(unsigned long long a,
                                                    unsigned long long b)
{
    unsigned long long d;
    asm("add.rn.f32x2 %0, %1, %2;" : "=l"(d) : "l"(a), "l"(b));
    return d;
}
__device__ __forceinline__ void upk2(unsigned long long v, float& lo, float& hi)
{
    asm("mov.b64 {%0, %1}, %2;" : "=f"(lo), "=f"(hi) : "l"(v));
}

// ---------------------------------------------------------------------------
// Reset scratch state so every graph replay is identical.
// ---------------------------------------------------------------------------
__global__ void init_kernel()
{
    int idx = blockIdx.x * blockDim.x + threadIdx.x;
    if (idx < Usz * Bsz) g_hT[0][idx] = 0.0f;
    if (idx < NCTA) g_flag[idx] = 0u;
}

// ---------------------------------------------------------------------------
// SGEMM: C[M,N] = A[M,K] * B[K,N], fp32 via fma.rn.f32x2.
// 128x128 CTA tile, BK=8, 256 threads, 8x8 register tile per thread,
// accumulators packed over the column dimension.
// Register-staged DOUBLE BUFFERING: LDG for tile i+1 issues before the
// compute on tile i, one __syncthreads per iteration.
// ---------------------------------------------------------------------------
__global__ __launch_bounds__(256, 2)
void sgemm128(const float* __restrict__ A, const float* __restrict__ Bm,
              float* __restrict__ C)
{
    const int N = Usz, K = Dsz;
    __shared__ __align__(16) float As[2][8][128];   // transposed A tiles
    __shared__ __align__(16) float Bs[2][8][128];

    const int tid = threadIdx.x;
    const int tx = tid & 15;        // 0..15 column group
    const int ty = tid >> 4;        // 0..15 row group
    const int row0 = blockIdx.y * 128;
    const int col0 = blockIdx.x * 128;

    const int arow = tid >> 1;            // 0..127
    const int acol = (tid & 1) << 2;      // 0 or 4
    const int brow = tid >> 5;            // 0..7
    const int bcol = (tid & 31) << 2;     // 0..124

    const float* Ap = A + (row0 + arow) * K + acol;
    const float* Bp = Bm + brow * N + col0 + bcol;

    unsigned long long acc[8][4];         // [row][colpair] packed fp32x2
#pragma unroll
    for (int i = 0; i < 8; ++i)
#pragma unroll
        for (int j = 0; j < 4; ++j) acc[i][j] = 0ull;

    // Preload tile 0
    float4 av = *(const float4*)(Ap);
    float4 bv = *(const float4*)(Bp);
    As[0][acol + 0][arow] = av.x;
    As[0][acol + 1][arow] = av.y;
    As[0][acol + 2][arow] = av.z;
    As[0][acol + 3][arow] = av.w;
    *(float4*)&Bs[0][brow][bcol] = bv;
    __syncthreads();

    for (int k0 = 0; k0 < K; k0 += 8) {
        const int buf = (k0 >> 3) & 1;

        // Issue next tile's global loads before the compute (latency overlap)
        if (k0 + 8 < K) {
            av = *(const float4*)(Ap + k0 + 8);
            bv = *(const float4*)(Bp + (k0 + 8) * N);
        }

#pragma unroll
        for (int kk = 0; kk < 8; ++kk) {
            float a[8];
            *(float4*)(a)     = *(const float4*)&As[buf][kk][ty * 4];
            *(float4*)(a + 4) = *(const float4*)&As[buf][kk][64 + ty * 4];
            ulonglong2 bL = *(const ulonglong2*)&Bs[buf][kk][tx * 4];
            ulonglong2 bH = *(const ulonglong2*)&Bs[buf][kk][64 + tx * 4];
#pragma unroll
            for (int i = 0; i < 8; ++i) {
                unsigned long long ad = pk2(a[i], a[i]);
                acc[i][0] = ffma2(ad, bL.x, acc[i][0]);
                acc[i][1] = ffma2(ad, bL.y, acc[i][1]);
                acc[i][2] = ffma2(ad, bH.x, acc[i][2]);
                acc[i][3] = ffma2(ad, bH.y, acc[i][3]);
            }
        }

        // Stage next tile into the other buffer (prev readers of it are done:
        // they synced at the end of the previous iteration)
        if (k0 + 8 < K) {
            const int nb = buf ^ 1;
            As[nb][acol + 0][arow] = av.x;
            As[nb][acol + 1][arow] = av.y;
            As[nb][acol + 2][arow] = av.z;
            As[nb][acol + 3][arow] = av.w;
            *(float4*)&Bs[nb][brow][bcol] = bv;
        }
        __syncthreads();
    }

#pragma unroll
    for (int i = 0; i < 8; ++i) {
        int r = row0 + ((i < 4) ? (ty * 4 + i) : (64 + ty * 4 + (i - 4)));
        ulonglong2 v0 = make_ulonglong2(acc[i][0], acc[i][1]);
        ulonglong2 v1 = make_ulonglong2(acc[i][2], acc[i][3]);
        *(ulonglong2*)&C[r * N + col0 + tx * 4] = v0;
        *(ulonglong2*)&C[r * N + col0 + 64 + tx * 4] = v1;
    }
}

// ---------------------------------------------------------------------------
// Persistent recurrent kernel, fp32x2. 128 CTAs (one wave), 256 threads.
// CTA = (column block of 16) x (batch half of 32): 64 x 2 = 128 CTAs.
// 8 warps split K (128 each); lane tile 4b x 4c packed over columns.
// Grid barrier: all-to-all flag array (2 L2 hops, no master-CTA broadcast).
// ---------------------------------------------------------------------------
__global__ __launch_bounds__(256, 1)
void rnn_kernel(const float* __restrict__ Wr, float* __restrict__ out)
{
    extern __shared__ char smraw[];
    float* Us  = (float*)smraw;                  // [1024][16], 64 KB
    float* red = (float*)(smraw + Usz * 16 * 4); // [8][512],   16 KB

    const int cta = blockIdx.x;
    const int tid = threadIdx.x;
    const int warp = tid >> 5;
    const int lane = tid & 31;
    const int c0 = (cta & 63) * 16;    // column base (16 cols)
    const int b0 = (cta >> 6) * 32;    // batch base  (32 rows)
    const int ct = (lane & 3) << 2;    // 0,4,8,12   (4 columns)
    const int bt = (lane >> 2) << 2;   // 0..28      (4 batch rows)
    const int k0 = warp * 128;         // this warp's K chunk

    // Stage U[:, c0..c0+15] into smem once; reused for all 512 steps.
    for (int idx = tid; idx < Usz * 16; idx += 256) {
        int k = idx >> 4;
        int j = idx & 15;
        Us[idx] = Wr[k * Usz + c0 + j];
    }
    __syncthreads();

    // Reduce-phase indices (1 packed column pair per thread, 256 pairs total)
    const int rlb = tid >> 3;          // local batch row 0..31
    const int rlc = (tid & 7) << 1;    // local column (even) 0..14

    for (int t = 0; t < Tsz; ++t) {
        const float* hT  = g_hT[t & 1];         // read  (zeroed for t=0)
        float*       hTn = g_hT[(t + 1) & 1];   // write

        // Prefetch this thread's xk pair (independent of h)
        const int go = ((b0 + rlb) * Tsz + t) * Usz + c0 + rlc;
        unsigned long long xk2 = *(const unsigned long long*)&out[go];

        unsigned long long acc[4][2];
#pragma unroll
        for (int i = 0; i < 4; ++i) { acc[i][0] = 0ull; acc[i][1] = 0ull; }

        const float* hp = hT + k0 * Bsz + b0 + bt;
        const float* up = Us + k0 * 16 + ct;
#pragma unroll 16
        for (int kk = 0; kk < 128; ++kk) {
            float4 hv = *(const float4*)(hp + kk * Bsz);          // 1 line/warp
            ulonglong2 uv = *(const ulonglong2*)(up + kk * 16);   // smem bcast
            unsigned long long h0 = pk2(hv.x, hv.x);
            unsigned long long h1 = pk2(hv.y, hv.y);
            unsigned long long h2 = pk2(hv.z, hv.z);
            unsigned long long h3 = pk2(hv.w, hv.w);
            acc[0][0] = ffma2(h0, uv.x, acc[0][0]);
            acc[0][1] = ffma2(h0, uv.y, acc[0][1]);
            acc[1][0] = ffma2(h1, uv.x, acc[1][0]);
            acc[1][1] = ffma2(h1, uv.y, acc[1][1]);
            acc[2][0] = ffma2(h2, uv.x, acc[2][0]);
            acc[2][1] = ffma2(h2, uv.y, acc[2][1]);
            acc[3][0] = ffma2(h3, uv.x, acc[3][0]);
            acc[3][1] = ffma2(h3, uv.y, acc[3][1]);
        }

        // Dump partials: red[warp][(local b)*16 + local c], 16B stores
#pragma unroll
        for (int i = 0; i < 4; ++i) {
            *(ulonglong2*)&red[warp * 512 + (bt + i) * 16 + ct] =
                make_ulonglong2(acc[i][0], acc[i][1]);
        }
        __syncthreads();

        // Reduce 8 K-partials (packed) + xk, relu, write out and hT(next).
        {
            const int oi = tid * 2;
            unsigned long long s = *(const unsigned long long*)&red[oi];
#pragma unroll
            for (int w = 1; w < 8; ++w)
                s = fadd2(s, *(const unsigned long long*)&red[w * 512 + oi]);
            s = fadd2(s, xk2);
            float v0, v1;
            upk2(s, v0, v1);
            v0 = fmaxf(v0, 0.0f);
            v1 = fmaxf(v1, 0.0f);
            *(unsigned long long*)&out[go] = pk2(v0, v1);
            hTn[(c0 + rlc) * Bsz + b0 + rlb] = v0;
            hTn[(c0 + rlc + 1) * Bsz + b0 + rlb] = v1;
        }

        // ---- grid barrier: all-to-all flags (2 L2 hops) ----
        const unsigned int tv = (unsigned int)t + 1u;
        __syncthreads();                   // CTA writes observed at CTA scope
        if (tid == 0) {
            __threadfence();               // promote observed writes to GPU scope
            g_flag[cta] = tv;              // arrive (distinct word per CTA)
        }
        if (tid < NCTA) {
            while (g_flag[tid] < tv) { }   // each thread spins on one flag
            __threadfence();               // order peer writes before our reads
        }
        __syncthreads();                   // propagate to whole CTA
    }
}

// ---------------------------------------------------------------------------
extern "C" void kernel_launch(void* const* d_in, const int* in_sizes, int n_in,
                              void* d_out, int out_size)
{
    (void)in_sizes; (void)n_in; (void)out_size;
    const float* x  = (const float*)d_in[0];   // [64,512,1024]
    const float* W  = (const float*)d_in[1];   // [1024,1024]
    const float* Wr = (const float*)d_in[2];   // [1024,1024]
    float* out = (float*)d_out;                // [64,512,1024]

    const int rnn_smem = Usz * 16 * 4 + 8 * 512 * 4;   // 80 KB dynamic
    cudaFuncSetAttribute(rnn_kernel,
                         cudaFuncAttributeMaxDynamicSharedMemorySize, rnn_smem);

    init_kernel<<<(Usz * Bsz + 255) / 256, 256>>>();

    dim3 g(Usz / 128, (Bsz * Tsz) / 128);      // 8 x 256 CTAs
    sgemm128<<<g, 256>>>(x, W, out);           // out = x @ W  (xk)

    rnn_kernel<<<NCTA, 256, rnn_smem>>>(Wr, out);   // sequential scan, in place
}

// round 13
// speedup vs baseline: 1.2299x; 1.2299x over previous
#include <cuda_runtime.h>

#define Bsz 64
#define Tsz 512
#define Dsz 1024
#define Usz 1024
#define NCTA 128

// Double-buffered transposed hidden state: hT[buf][k*64 + b]
__device__ __align__(16) float g_hT[2][Usz * Bsz];
__device__ volatile unsigned int g_flag[NCTA];
__device__ volatile unsigned int g_go;

// ---------------------------------------------------------------------------
// Packed fp32x2 helpers (sm_100+). Numerics identical to scalar FFMA.
// ---------------------------------------------------------------------------
__device__ __forceinline__ unsigned long long pk2(float lo, float hi)
{
    unsigned long long d;
    asm("mov.b64 %0, {%1, %2};" : "=l"(d) : "f"(lo), "f"(hi));
    return d;
}
__device__ __forceinline__ unsigned long long ffma2(unsigned long long a,
                                                    unsigned long long b,
                                                    unsigned long long c)
{
    unsigned long long d;
    asm("fma.rn.f32x2 %0, %1, %2, %3;" : "=l"(d) : "l"(a), "l"(b), "l"(c));
    return d;
}
__device__ __forceinline__ unsigned long long fadd2(unsigned long long a,
                                                    unsigned long long b)
{
    unsigned long long d;
    asm("add.rn.f32x2 %0, %1, %2;" : "=l"(d) : "l"(a), "l"(b));
    return d;
}
__device__ __forceinline__ void upk2(unsigned long long v, float& lo, float& hi)
{
    asm("mov.b64 {%0, %1}, %2;" : "=f"(lo), "=f"(hi) : "l"(v));
}

// ---------------------------------------------------------------------------
// Reset scratch state so every graph replay is identical.
// ---------------------------------------------------------------------------
__global__ void init_kernel()
{
    int idx = blockIdx.x * blockDim.x + threadIdx.x;
    if (idx < Usz * Bsz) g_hT[0][idx] = 0.0f;
    if (idx < NCTA) g_flag[idx] = 0u;
    if (idx == 0) g_go = 0u;
}

// ---------------------------------------------------------------------------
// SGEMM: C[M,N] = A[M,K] * B[K,N], fp32 via fma.rn.f32x2.
// 128x128 CTA tile, BK=8, 256 threads, 8x8 register tile per thread,
// accumulators packed over the column dimension. (Proven R8 version.)
// ---------------------------------------------------------------------------
__global__ __launch_bounds__(256, 2)
void sgemm128(const float* __restrict__ A, const float* __restrict__ Bm,
              float* __restrict__ C)
{
    const int N = Usz, K = Dsz;
    __shared__ __align__(16) float As[8][128];   // transposed A tile
    __shared__ __align__(16) float Bs[8][128];

    const int tid = threadIdx.x;
    const int tx = tid & 15;        // 0..15 column group
    const int ty = tid >> 4;        // 0..15 row group
    const int row0 = blockIdx.y * 128;
    const int col0 = blockIdx.x * 128;

    const int arow = tid >> 1;            // 0..127
    const int acol = (tid & 1) << 2;      // 0 or 4
    const int brow = tid >> 5;            // 0..7
    const int bcol = (tid & 31) << 2;     // 0..124

    const float* Ap = A + (row0 + arow) * K + acol;
    const float* Bp = Bm + brow * N + col0 + bcol;

    unsigned long long acc[8][4];         // [row][colpair] packed fp32x2
#pragma unroll
    for (int i = 0; i < 8; ++i)
#pragma unroll
        for (int j = 0; j < 4; ++j) acc[i][j] = 0ull;

    for (int k0 = 0; k0 < K; k0 += 8) {
        float4 av = *(const float4*)(Ap + k0);
        float4 bv = *(const float4*)(Bp + k0 * N);
        As[acol + 0][arow] = av.x;
        As[acol + 1][arow] = av.y;
        As[acol + 2][arow] = av.z;
        As[acol + 3][arow] = av.w;
        *(float4*)&Bs[brow][bcol] = bv;
        __syncthreads();
#pragma unroll
        for (int kk = 0; kk < 8; ++kk) {
            float a[8];
            *(float4*)(a)     = *(const float4*)&As[kk][ty * 4];
            *(float4*)(a + 4) = *(const float4*)&As[kk][64 + ty * 4];
            ulonglong2 bL = *(const ulonglong2*)&Bs[kk][tx * 4];       // cols 0-3
            ulonglong2 bH = *(const ulonglong2*)&Bs[kk][64 + tx * 4];  // cols 4-7
#pragma unroll
            for (int i = 0; i < 8; ++i) {
                unsigned long long ad = pk2(a[i], a[i]);
                acc[i][0] = ffma2(ad, bL.x, acc[i][0]);
                acc[i][1] = ffma2(ad, bL.y, acc[i][1]);
                acc[i][2] = ffma2(ad, bH.x, acc[i][2]);
                acc[i][3] = ffma2(ad, bH.y, acc[i][3]);
            }
        }
        __syncthreads();
    }

#pragma unroll
    for (int i = 0; i < 8; ++i) {
        int r = row0 + ((i < 4) ? (ty * 4 + i) : (64 + ty * 4 + (i - 4)));
        ulonglong2 v0 = make_ulonglong2(acc[i][0], acc[i][1]);
        ulonglong2 v1 = make_ulonglong2(acc[i][2], acc[i][3]);
        *(ulonglong2*)&C[r * N + col0 + tx * 4] = v0;
        *(ulonglong2*)&C[r * N + col0 + 64 + tx * 4] = v1;
    }
}

// ---------------------------------------------------------------------------
// Persistent recurrent kernel, fp32x2 PACKED OVER BATCH. 128 CTAs, 256 thr.
// CTA = (column block of 16) x (batch half of 32): 64 x 2 = 128 CTAs.
// U is stored PRE-DUPLICATED in smem as (u,u) packed pairs, so the inner
// loop needs ZERO pack MOVs: h pairs come free from the float4 LDG
// (consecutive registers = packed pair), U pairs come free from LDS.128.
// Inner loop/iter/warp: 1 LDG.128 + 2 LDS.128 + 8 FFMA2.
// Smem: Us2 128KB + red 16KB = 144KB (occ 1). Barrier: proven master-CTA.
// ---------------------------------------------------------------------------
__global__ __launch_bounds__(256, 1)
void rnn_kernel(const float* __restrict__ Wr, float* __restrict__ out)
{
    extern __shared__ char smraw[];
    unsigned long long* Us2 =
        (unsigned long long*)smraw;                    // [1024][16] dup pairs, 128 KB
    unsigned long long* red =
        (unsigned long long*)(smraw + Usz * 16 * 8);   // [8][256] packed, 16 KB

    const int cta = blockIdx.x;
    const int tid = threadIdx.x;
    const int warp = tid >> 5;
    const int lane = tid & 31;
    const int c0 = (cta & 63) * 16;    // column base (16 cols)
    const int b0 = (cta >> 6) * 32;    // batch base  (32 rows)
    const int ct = (lane & 3) << 2;    // 0,4,8,12   (4 columns)
    const int bt = (lane >> 2) << 2;   // 0..28      (4 batch rows = 2 pairs)
    const int k0 = warp * 128;         // this warp's K chunk

    // Stage U[:, c0..c0+15] into smem pre-duplicated; reused for 512 steps.
    for (int idx = tid; idx < Usz * 16; idx += 256) {
        int k = idx >> 4;
        int j = idx & 15;
        float u = Wr[k * Usz + c0 + j];
        Us2[idx] = pk2(u, u);
    }
    __syncthreads();

    // Reduce-phase indices: 256 packed pairs = 16 bpairs x 16 cols.
    // col varies fastest across tid so out accesses coalesce.
    const int rcol = tid & 15;         // local column 0..15
    const int rbp  = tid >> 4;         // local batch pair 0..15

    for (int t = 0; t < Tsz; ++t) {
        const float* hT  = g_hT[t & 1];         // read  (zeroed for t=0)
        float*       hTn = g_hT[(t + 1) & 1];   // write

        // Prefetch this thread's xk scalars (independent of h)
        const int b_lo = b0 + rbp * 2;
        const int goc  = c0 + rcol;
        const int go0 = (b_lo * Tsz + t) * Usz + goc;
        const int go1 = ((b_lo + 1) * Tsz + t) * Usz + goc;
        float xk0 = out[go0];
        float xk1 = out[go1];

        unsigned long long acc[4][2];   // [col][batchpair]
#pragma unroll
        for (int i = 0; i < 4; ++i) { acc[i][0] = 0ull; acc[i][1] = 0ull; }

        const float* hp = hT + k0 * Bsz + b0 + bt;
        const unsigned long long* up = Us2 + k0 * 16 + ct;
#pragma unroll 16
        for (int kk = 0; kk < 128; ++kk) {
            // h[k][bt..bt+3]: consecutive regs reinterpret as 2 packed pairs
            ulonglong2 hv = *(const ulonglong2*)(hp + kk * Bsz);
            // 4 dup'd U cols = 2 x LDS.128
            ulonglong2 uA = *(const ulonglong2*)(up + kk * 16);      // cols ct,ct+1
            ulonglong2 uB = *(const ulonglong2*)(up + kk * 16 + 2);  // cols ct+2,ct+3
            acc[0][0] = ffma2(uA.x, hv.x, acc[0][0]);
            acc[0][1] = ffma2(uA.x, hv.y, acc[0][1]);
            acc[1][0] = ffma2(uA.y, hv.x, acc[1][0]);
            acc[1][1] = ffma2(uA.y, hv.y, acc[1][1]);
            acc[2][0] = ffma2(uB.x, hv.x, acc[2][0]);
            acc[2][1] = ffma2(uB.x, hv.y, acc[2][1]);
            acc[3][0] = ffma2(uB.y, hv.x, acc[3][0]);
            acc[3][1] = ffma2(uB.y, hv.y, acc[3][1]);
        }

        // Dump partials: red[warp][bpair*16 + col], 16B stores
        // (adjacent cols ct+i,ct+i+1 are contiguous -> ulonglong2)
        const int bp0 = bt >> 1;
#pragma unroll
        for (int p = 0; p < 2; ++p) {
            *(ulonglong2*)&red[warp * 256 + (bp0 + p) * 16 + ct] =
                make_ulonglong2(acc[0][p], acc[1][p]);
            *(ulonglong2*)&red[warp * 256 + (bp0 + p) * 16 + ct + 2] =
                make_ulonglong2(acc[2][p], acc[3][p]);
        }
        __syncthreads();

        // Reduce 8 K-partials (packed over batch) + xk, relu, write out & hT.
        {
            unsigned long long s = red[tid];
#pragma unroll
            for (int w = 1; w < 8; ++w)
                s = fadd2(s, red[w * 256 + tid]);
            float v0, v1;
            upk2(s, v0, v1);
            v0 = fmaxf(v0 + xk0, 0.0f);
            v1 = fmaxf(v1 + xk1, 0.0f);
            out[go0] = v0;
            out[go1] = v1;
            // hT[k=c][b], batch pair adjacent -> one 8B store
            *(unsigned long long*)&hTn[goc * Bsz + b_lo] = pk2(v0, v1);
        }

        // ---- grid barrier (proven: flag array + master-CTA broadcast) ----
        unsigned int tv = (unsigned int)t + 1u;
        __syncthreads();
        if (tid == 0) {
            __threadfence();
            g_flag[cta] = tv;              // parallel arrives (distinct words)
        }
        if (cta == 0) {
            if (tid < NCTA) {
                while (g_flag[tid] < tv) { }
            }
            __syncthreads();
            if (tid == 0) {
                __threadfence();
                g_go = tv;                 // single release word
            }
        }
        if (tid == 0) {
            while (g_go < tv) { }
            __threadfence();
        }
        __syncthreads();
    }
}

// ---------------------------------------------------------------------------
extern "C" void kernel_launch(void* const* d_in, const int* in_sizes, int n_in,
                              void* d_out, int out_size)
{
    (void)in_sizes; (void)n_in; (void)out_size;
    const float* x  = (const float*)d_in[0];   // [64,512,1024]
    const float* W  = (const float*)d_in[1];   // [1024,1024]
    const float* Wr = (const float*)d_in[2];   // [1024,1024]
    float* out = (float*)d_out;                // [64,512,1024]

    const int rnn_smem = Usz * 16 * 8 + 8 * 256 * 8;   // 128KB + 16KB = 144 KB
    cudaFuncSetAttribute(rnn_kernel,
                         cudaFuncAttributeMaxDynamicSharedMemorySize, rnn_smem);

    init_kernel<<<(Usz * Bsz + 255) / 256, 256>>>();

    dim3 g(Usz / 128, (Bsz * Tsz) / 128);      // 8 x 256 CTAs
    sgemm128<<<g, 256>>>(x, W, out);           // out = x @ W  (xk)

    rnn_kernel<<<NCTA, 256, rnn_smem>>>(Wr, out);   // sequential scan, in place
}

// round 14
// speedup vs baseline: 1.6295x; 1.3249x over previous
#include <cuda_runtime.h>
#include <cuda_bf16.h>

#define Bsz 64
#define Tsz 512
#define Dsz 1024
#define Usz 1024
#define NCTA 128
#define Msz (Bsz * Tsz)

// Double-buffered transposed hidden state: hT[buf][k*64 + b]
__device__ __align__(16) float g_hT[2][Usz * Bsz];
__device__ volatile unsigned int g_flag[NCTA];
__device__ volatile unsigned int g_go;

// Split-precision bf16 copies of x and W (written by cvt_split every call).
__device__ __align__(16) __nv_bfloat16 g_xhi[Msz * Dsz];   // 64 MB
__device__ __align__(16) __nv_bfloat16 g_xlo[Msz * Dsz];   // 64 MB
__device__ __align__(16) __nv_bfloat16 g_whi[Dsz * Usz];   // 2 MB
__device__ __align__(16) __nv_bfloat16 g_wlo[Dsz * Usz];   // 2 MB

// ---------------------------------------------------------------------------
// Packed fp32x2 helpers (sm_100+). Numerics identical to scalar FFMA.
// ---------------------------------------------------------------------------
__device__ __forceinline__ unsigned long long pk2(float lo, float hi)
{
    unsigned long long d;
    asm("mov.b64 %0, {%1, %2};" : "=l"(d) : "f"(lo), "f"(hi));
    return d;
}
__device__ __forceinline__ unsigned long long ffma2(unsigned long long a,
                                                    unsigned long long b,
                                                    unsigned long long c)
{
    unsigned long long d;
    asm("fma.rn.f32x2 %0, %1, %2, %3;" : "=l"(d) : "l"(a), "l"(b), "l"(c));
    return d;
}
__device__ __forceinline__ unsigned long long fadd2(unsigned long long a,
                                                    unsigned long long b)
{
    unsigned long long d;
    asm("add.rn.f32x2 %0, %1, %2;" : "=l"(d) : "l"(a), "l"(b));
    return d;
}
__device__ __forceinline__ void upk2(unsigned long long v, float& lo, float& hi)
{
    asm("mov.b64 {%0, %1}, %2;" : "=f"(lo), "=f"(hi) : "l"(v));
}

// ---------------------------------------------------------------------------
// MMA helpers
// ---------------------------------------------------------------------------
__device__ __forceinline__ unsigned su32(const void* p)
{
    return (unsigned)__cvta_generic_to_shared(p);
}
__device__ __forceinline__ void ldsm4(unsigned* r, unsigned addr)
{
    asm volatile("ldmatrix.sync.aligned.m8n8.x4.shared.b16 {%0,%1,%2,%3}, [%4];"
                 : "=r"(r[0]), "=r"(r[1]), "=r"(r[2]), "=r"(r[3]) : "r"(addr));
}
__device__ __forceinline__ void ldsm4t(unsigned* r, unsigned addr)
{
    asm volatile("ldmatrix.sync.aligned.m8n8.x4.trans.shared.b16 {%0,%1,%2,%3}, [%4];"
                 : "=r"(r[0]), "=r"(r[1]), "=r"(r[2]), "=r"(r[3]) : "r"(addr));
}
__device__ __forceinline__ void mma16816(float* d, const unsigned* a, const unsigned* b)
{
    asm volatile(
        "mma.sync.aligned.m16n8k16.row.col.f32.bf16.bf16.f32 "
        "{%0,%1,%2,%3}, {%4,%5,%6,%7}, {%8,%9}, {%0,%1,%2,%3};"
        : "+f"(d[0]), "+f"(d[1]), "+f"(d[2]), "+f"(d[3])
        : "r"(a[0]), "r"(a[1]), "r"(a[2]), "r"(a[3]), "r"(b[0]), "r"(b[1]));
}

// ---------------------------------------------------------------------------
// Reset scratch state so every graph replay is identical.
// ---------------------------------------------------------------------------
__global__ void init_kernel()
{
    int idx = blockIdx.x * blockDim.x + threadIdx.x;
    if (idx < Usz * Bsz) g_hT[0][idx] = 0.0f;
    if (idx < NCTA) g_flag[idx] = 0u;
    if (idx == 0) g_go = 0u;
}

// ---------------------------------------------------------------------------
// Split fp32 -> (hi, lo) bf16 pair: v = hi + lo + O(2^-17 * v).
// ---------------------------------------------------------------------------
__global__ void cvt_split(const float* __restrict__ src,
                          __nv_bfloat16* __restrict__ hi,
                          __nv_bfloat16* __restrict__ lo, int n4)
{
    int i = blockIdx.x * blockDim.x + threadIdx.x;
    if (i >= n4) return;
    float4 v = ((const float4*)src)[i];
    __nv_bfloat16 h0 = __float2bfloat16(v.x);
    __nv_bfloat16 h1 = __float2bfloat16(v.y);
    __nv_bfloat16 h2 = __float2bfloat16(v.z);
    __nv_bfloat16 h3 = __float2bfloat16(v.w);
    __nv_bfloat16 l0 = __float2bfloat16(v.x - __bfloat162float(h0));
    __nv_bfloat16 l1 = __float2bfloat16(v.y - __bfloat162float(h1));
    __nv_bfloat16 l2 = __float2bfloat16(v.z - __bfloat162float(h2));
    __nv_bfloat16 l3 = __float2bfloat16(v.w - __bfloat162float(h3));
    __nv_bfloat162 ph0; ph0.x = h0; ph0.y = h1;
    __nv_bfloat162 ph1; ph1.x = h2; ph1.y = h3;
    __nv_bfloat162 pl0; pl0.x = l0; pl0.y = l1;
    __nv_bfloat162 pl1; pl1.x = l2; pl1.y = l3;
    ((__nv_bfloat162*)hi)[i * 2]     = ph0;
    ((__nv_bfloat162*)hi)[i * 2 + 1] = ph1;
    ((__nv_bfloat162*)lo)[i * 2]     = pl0;
    ((__nv_bfloat162*)lo)[i * 2 + 1] = pl1;
}

// ---------------------------------------------------------------------------
// Split-bf16 tensor-core SGEMM: C = Ahi*Bhi + Ahi*Blo + Alo*Bhi (fp32 accum).
// CTA tile 128x128, K-tile 32, 256 threads = 8 warps (2M x 4N), warp tile
// 64x32, mma.m16n8k16. A rows padded to 40 bf16, B rows to 136 bf16 for
// conflict-free ldmatrix. Register-staged prefetch of the next K-tile.
// ---------------------------------------------------------------------------
__global__ __launch_bounds__(256)
void sgemm_mma(const __nv_bfloat16* __restrict__ Ahi,
               const __nv_bfloat16* __restrict__ Alo,
               const __nv_bfloat16* __restrict__ Bhi,
               const __nv_bfloat16* __restrict__ Blo,
               float* __restrict__ C)
{
    const int K = Dsz, N = Usz;
    __shared__ __align__(16) __nv_bfloat16 sAhi[128 * 40];
    __shared__ __align__(16) __nv_bfloat16 sAlo[128 * 40];
    __shared__ __align__(16) __nv_bfloat16 sBhi[32 * 136];
    __shared__ __align__(16) __nv_bfloat16 sBlo[32 * 136];

    const int tid  = threadIdx.x;
    const int lane = tid & 31;
    const int w    = tid >> 5;
    const int m0   = (w & 1) * 64;      // warp M offset
    const int n0   = (w >> 1) * 32;     // warp N offset
    const int row0 = blockIdx.y * 128;
    const int col0 = blockIdx.x * 128;

    const int arow = tid >> 1;          // 0..127
    const int ac   = (tid & 1) * 16;    // 0 or 16 (bf16 elems)
    const int brow = tid >> 3;          // 0..31
    const int bc   = (tid & 7) * 16;    // 0..112

    const __nv_bfloat16* Aph = Ahi + (row0 + arow) * K + ac;
    const __nv_bfloat16* Apl = Alo + (row0 + arow) * K + ac;
    const __nv_bfloat16* Bph = Bhi + brow * N + col0 + bc;
    const __nv_bfloat16* Bpl = Blo + brow * N + col0 + bc;

    float acc[4][4][4];
#pragma unroll
    for (int i = 0; i < 4; ++i)
#pragma unroll
        for (int j = 0; j < 4; ++j)
#pragma unroll
            for (int q = 0; q < 4; ++q) acc[i][j][q] = 0.0f;

    // Prefetch tile 0
    uint4 rah0 = *(const uint4*)(Aph);
    uint4 rah1 = *(const uint4*)(Aph + 8);
    uint4 ral0 = *(const uint4*)(Apl);
    uint4 ral1 = *(const uint4*)(Apl + 8);
    uint4 rbh0 = *(const uint4*)(Bph);
    uint4 rbh1 = *(const uint4*)(Bph + 8);
    uint4 rbl0 = *(const uint4*)(Bpl);
    uint4 rbl1 = *(const uint4*)(Bpl + 8);

    for (int k0 = 0; k0 < K; k0 += 32) {
        // Stage current tile
        *(uint4*)&sAhi[arow * 40 + ac]     = rah0;
        *(uint4*)&sAhi[arow * 40 + ac + 8] = rah1;
        *(uint4*)&sAlo[arow * 40 + ac]     = ral0;
        *(uint4*)&sAlo[arow * 40 + ac + 8] = ral1;
        *(uint4*)&sBhi[brow * 136 + bc]     = rbh0;
        *(uint4*)&sBhi[brow * 136 + bc + 8] = rbh1;
        *(uint4*)&sBlo[brow * 136 + bc]     = rbl0;
        *(uint4*)&sBlo[brow * 136 + bc + 8] = rbl1;
        __syncthreads();

        // Prefetch next tile while computing this one
        if (k0 + 32 < K) {
            rah0 = *(const uint4*)(Aph + k0 + 32);
            rah1 = *(const uint4*)(Aph + k0 + 40);
            ral0 = *(const uint4*)(Apl + k0 + 32);
            ral1 = *(const uint4*)(Apl + k0 + 40);
            rbh0 = *(const uint4*)(Bph + (k0 + 32) * N);
            rbh1 = *(const uint4*)(Bph + (k0 + 32) * N + 8);
            rbl0 = *(const uint4*)(Bpl + (k0 + 32) * N);
            rbl1 = *(const uint4*)(Bpl + (k0 + 32) * N + 8);
        }

#pragma unroll
        for (int kk = 0; kk < 32; kk += 16) {
            unsigned ah[4][4], al[4][4], bh[4][2], bl[4][2];
#pragma unroll
            for (int i = 0; i < 4; ++i) {
                int row = m0 + i * 16 + (lane & 15);
                int ck  = kk + ((lane >> 4) << 3);
                ldsm4(ah[i], su32(&sAhi[row * 40 + ck]));
                ldsm4(al[i], su32(&sAlo[row * 40 + ck]));
            }
#pragma unroll
            for (int nb = 0; nb < 2; ++nb) {
                int kr = kk + (((lane >> 3) & 1) << 3) + (lane & 7);
                int nc = n0 + nb * 16 + ((lane >> 4) << 3);
                unsigned r[4];
                ldsm4t(r, su32(&sBhi[kr * 136 + nc]));
                bh[nb * 2][0] = r[0]; bh[nb * 2][1] = r[1];
                bh[nb * 2 + 1][0] = r[2]; bh[nb * 2 + 1][1] = r[3];
                ldsm4t(r, su32(&sBlo[kr * 136 + nc]));
                bl[nb * 2][0] = r[0]; bl[nb * 2][1] = r[1];
                bl[nb * 2 + 1][0] = r[2]; bl[nb * 2 + 1][1] = r[3];
            }
#pragma unroll
            for (int i = 0; i < 4; ++i)
#pragma unroll
                for (int j = 0; j < 4; ++j) {
                    mma16816(acc[i][j], al[i], bh[j]);   // lo*hi
                    mma16816(acc[i][j], ah[i], bl[j]);   // hi*lo
                    mma16816(acc[i][j], ah[i], bh[j]);   // hi*hi
                }
        }
        __syncthreads();
    }

    // Epilogue: m16n8 C fragment -> fp32 gmem
#pragma unroll
    for (int i = 0; i < 4; ++i) {
#pragma unroll
        for (int j = 0; j < 4; ++j) {
            int r  = row0 + m0 + i * 16 + (lane >> 2);
            int c  = col0 + n0 + j * 8 + 2 * (lane & 3);
            *(float2*)&C[r * N + c]       = make_float2(acc[i][j][0], acc[i][j][1]);
            *(float2*)&C[(r + 8) * N + c] = make_float2(acc[i][j][2], acc[i][j][3]);
        }
    }
}

// ---------------------------------------------------------------------------
// Persistent recurrent kernel, fp32x2 (EXACT proven R8 version, 5294us).
// 128 CTAs, 256 thr. CTA = (16 cols) x (32 batch). 8 warps split K.
// ---------------------------------------------------------------------------
__global__ __launch_bounds__(256, 1)
void rnn_kernel(const float* __restrict__ Wr, float* __restrict__ out)
{
    extern __shared__ char smraw[];
    float* Us  = (float*)smraw;                  // [1024][16], 64 KB
    float* red = (float*)(smraw + Usz * 16 * 4); // [8][512],   16 KB

    const int cta = blockIdx.x;
    const int tid = threadIdx.x;
    const int warp = tid >> 5;
    const int lane = tid & 31;
    const int c0 = (cta & 63) * 16;    // column base (16 cols)
    const int b0 = (cta >> 6) * 32;    // batch base  (32 rows)
    const int ct = (lane & 3) << 2;    // 0,4,8,12   (4 columns)
    const int bt = (lane >> 2) << 2;   // 0..28      (4 batch rows)
    const int k0 = warp * 128;         // this warp's K chunk

    // Stage U[:, c0..c0+15] into smem once; reused for all 512 steps.
    for (int idx = tid; idx < Usz * 16; idx += 256) {
        int k = idx >> 4;
        int j = idx & 15;
        Us[idx] = Wr[k * Usz + c0 + j];
    }
    __syncthreads();

    // Reduce-phase indices (1 packed column pair per thread, 256 pairs total)
    const int rlb = tid >> 3;          // local batch row 0..31
    const int rlc = (tid & 7) << 1;    // local column (even) 0..14

    for (int t = 0; t < Tsz; ++t) {
        const float* hT  = g_hT[t & 1];         // read  (zeroed for t=0)
        float*       hTn = g_hT[(t + 1) & 1];   // write

        // Prefetch this thread's xk pair (independent of h)
        const int go = ((b0 + rlb) * Tsz + t) * Usz + c0 + rlc;
        unsigned long long xk2 = *(const unsigned long long*)&out[go];

        unsigned long long acc[4][2];
#pragma unroll
        for (int i = 0; i < 4; ++i) { acc[i][0] = 0ull; acc[i][1] = 0ull; }

        const float* hp = hT + k0 * Bsz + b0 + bt;
        const float* up = Us + k0 * 16 + ct;
#pragma unroll 16
        for (int kk = 0; kk < 128; ++kk) {
            float4 hv = *(const float4*)(hp + kk * Bsz);          // 1 line/warp
            ulonglong2 uv = *(const ulonglong2*)(up + kk * 16);   // smem bcast
            unsigned long long h0 = pk2(hv.x, hv.x);
            unsigned long long h1 = pk2(hv.y, hv.y);
            unsigned long long h2 = pk2(hv.z, hv.z);
            unsigned long long h3 = pk2(hv.w, hv.w);
            acc[0][0] = ffma2(h0, uv.x, acc[0][0]);
            acc[0][1] = ffma2(h0, uv.y, acc[0][1]);
            acc[1][0] = ffma2(h1, uv.x, acc[1][0]);
            acc[1][1] = ffma2(h1, uv.y, acc[1][1]);
            acc[2][0] = ffma2(h2, uv.x, acc[2][0]);
            acc[2][1] = ffma2(h2, uv.y, acc[2][1]);
            acc[3][0] = ffma2(h3, uv.x, acc[3][0]);
            acc[3][1] = ffma2(h3, uv.y, acc[3][1]);
        }

        // Dump partials: red[warp][(local b)*16 + local c], 16B stores
#pragma unroll
        for (int i = 0; i < 4; ++i) {
            *(ulonglong2*)&red[warp * 512 + (bt + i) * 16 + ct] =
                make_ulonglong2(acc[i][0], acc[i][1]);
        }
        __syncthreads();

        // Reduce 8 K-partials (packed) + xk, relu, write out and hT(next).
        {
            const int oi = tid * 2;
            unsigned long long s = *(const unsigned long long*)&red[oi];
#pragma unroll
            for (int w = 1; w < 8; ++w)
                s = fadd2(s, *(const unsigned long long*)&red[w * 512 + oi]);
            s = fadd2(s, xk2);
            float v0, v1;
            upk2(s, v0, v1);
            v0 = fmaxf(v0, 0.0f);
            v1 = fmaxf(v1, 0.0f);
            *(unsigned long long*)&out[go] = pk2(v0, v1);
            hTn[(c0 + rlc) * Bsz + b0 + rlb] = v0;
            hTn[(c0 + rlc + 1) * Bsz + b0 + rlb] = v1;
        }

        // ---- grid barrier (proven: flag array + master-CTA broadcast) ----
        unsigned int tv = (unsigned int)t + 1u;
        __syncthreads();
        if (tid == 0) {
            __threadfence();
            g_flag[cta] = tv;              // parallel arrives (distinct words)
        }
        if (cta == 0) {
            if (tid < NCTA) {
                while (g_flag[tid] < tv) { }
            }
            __syncthreads();
            if (tid == 0) {
                __threadfence();
                g_go = tv;                 // single release word
            }
        }
        if (tid == 0) {
            while (g_go < tv) { }
            __threadfence();
        }
        __syncthreads();
    }
}

// ---------------------------------------------------------------------------
extern "C" void kernel_launch(void* const* d_in, const int* in_sizes, int n_in,
                              void* d_out, int out_size)
{
    (void)in_sizes; (void)n_in; (void)out_size;
    const float* x  = (const float*)d_in[0];   // [64,512,1024]
    const float* W  = (const float*)d_in[1];   // [1024,1024]
    const float* Wr = (const float*)d_in[2];   // [1024,1024]
    float* out = (float*)d_out;                // [64,512,1024]

    __nv_bfloat16 *xhi, *xlo, *whi, *wlo;
    cudaGetSymbolAddress((void**)&xhi, g_xhi);
    cudaGetSymbolAddress((void**)&xlo, g_xlo);
    cudaGetSymbolAddress((void**)&whi, g_whi);
    cudaGetSymbolAddress((void**)&wlo, g_wlo);

    const int rnn_smem = Usz * 16 * 4 + 8 * 512 * 4;   // 80 KB dynamic
    cudaFuncSetAttribute(rnn_kernel,
                         cudaFuncAttributeMaxDynamicSharedMemorySize, rnn_smem);

    init_kernel<<<(Usz * Bsz + 255) / 256, 256>>>();

    // Split x and W into bf16 hi/lo pairs
    cvt_split<<<(Msz * Dsz / 4 + 255) / 256, 256>>>(x, xhi, xlo, Msz * Dsz / 4);
    cvt_split<<<(Dsz * Usz / 4 + 255) / 256, 256>>>(W, whi, wlo, Dsz * Usz / 4);

    // xk = x @ W via split-bf16 tensor cores
    dim3 g(Usz / 128, Msz / 128);              // 8 x 256 CTAs
    sgemm_mma<<<g, 256>>>(xhi, xlo, whi, wlo, out);

    rnn_kernel<<<NCTA, 256, rnn_smem>>>(Wr, out);   // sequential scan, in place
}